// round 11
// baseline (speedup 1.0000x reference)
#include <cuda_runtime.h>
#include <cuda_bf16.h>
#include <cstdint>
#include <math.h>

#define BB 4
#define LL 2048
#define DD 1024
#define HH 16
#define DKK 64
#define BH (BB*HH)        // 64
#define MROWS (BB*LL)     // 8192

#define SPAD 40           // smem row stride (bf16) for K=32 chunks
#define SPAD2 72          // smem row stride (bf16) for K=64 tiles (scores)

// pipelined-stage smem layout (proj / av): per stage
#define ST_AH 0
#define ST_AL 10240       // 128*40*2
#define ST_BH 20480
#define ST_BL 25600       // 64*40*2
#define STAGE_BYTES 30720
#define PIPE_SMEM (2*STAGE_BYTES)      // 61440

// scores smem layout
#define SC_QH 0
#define SC_QL 18432       // 128*72*2
#define SC_KH 36864
#define SC_KL 55296
#define SC_SMEM 73728

typedef unsigned short u16;

// ---------------- device scratch (allocation-free) ----------------
__device__ u16 g_xh[(size_t)MROWS * DD], g_xl[(size_t)MROWS * DD];
__device__ u16 g_wh[(size_t)4 * DD * DD], g_wl[(size_t)4 * DD * DD];
__device__ u16 g_qh[(size_t)BH * LL * DKK], g_ql[(size_t)BH * LL * DKK];
__device__ u16 g_kh[(size_t)BH * LL * DKK], g_kl[(size_t)BH * LL * DKK];
__device__ u16 g_vth[(size_t)BH * DKK * LL], g_vtl[(size_t)BH * DKK * LL];
__device__ u16 g_och[(size_t)MROWS * DD], g_ocl[(size_t)MROWS * DD];
__device__ float g_attn_scratch[(size_t)BH * LL * LL]; // fallback

// ---------------- helpers ----------------
__device__ __forceinline__ uint32_t s32(const void* p) {
    return (uint32_t)__cvta_generic_to_shared(p);
}

#define LDSM_X4(R, a)                                                          \
    asm volatile("ldmatrix.sync.aligned.m8n8.x4.shared.b16 {%0,%1,%2,%3}, [%4];" \
        : "=r"((R)[0]), "=r"((R)[1]), "=r"((R)[2]), "=r"((R)[3]) : "r"(a))
#define LDSM_X2(R, a)                                                          \
    asm volatile("ldmatrix.sync.aligned.m8n8.x2.shared.b16 {%0,%1}, [%2];"     \
        : "=r"((R)[0]), "=r"((R)[1]) : "r"(a))

__device__ __forceinline__ void mma_bf16(float* c, const uint32_t* a, const uint32_t* b) {
    asm volatile(
        "mma.sync.aligned.m16n8k16.row.col.f32.bf16.bf16.f32 "
        "{%0,%1,%2,%3}, {%4,%5,%6,%7}, {%8,%9}, {%0,%1,%2,%3};"
        : "+f"(c[0]), "+f"(c[1]), "+f"(c[2]), "+f"(c[3])
        : "r"(a[0]), "r"(a[1]), "r"(a[2]), "r"(a[3]), "r"(b[0]), "r"(b[1]));
}

__device__ __forceinline__ void cvt_split(const float4& v, uint2& hv, uint2& lv) {
    __nv_bfloat16 h0 = __float2bfloat16(v.x), h1 = __float2bfloat16(v.y);
    __nv_bfloat16 h2 = __float2bfloat16(v.z), h3 = __float2bfloat16(v.w);
    __nv_bfloat16 l0 = __float2bfloat16(v.x - __bfloat162float(h0));
    __nv_bfloat16 l1 = __float2bfloat16(v.y - __bfloat162float(h1));
    __nv_bfloat16 l2 = __float2bfloat16(v.z - __bfloat162float(h2));
    __nv_bfloat16 l3 = __float2bfloat16(v.w - __bfloat162float(h3));
    hv.x = ((uint32_t)__bfloat16_as_ushort(h1) << 16) | __bfloat16_as_ushort(h0);
    hv.y = ((uint32_t)__bfloat16_as_ushort(h3) << 16) | __bfloat16_as_ushort(h2);
    lv.x = ((uint32_t)__bfloat16_as_ushort(l1) << 16) | __bfloat16_as_ushort(l0);
    lv.y = ((uint32_t)__bfloat16_as_ushort(l3) << 16) | __bfloat16_as_ushort(l2);
}

__device__ __forceinline__ void split8(const float* v, uint4& h4, uint4& l4) {
    uint32_t h[8], l[8];
    #pragma unroll
    for (int e = 0; e < 8; e++) {
        __nv_bfloat16 hb = __float2bfloat16(v[e]);
        h[e] = __bfloat16_as_ushort(hb);
        l[e] = __bfloat16_as_ushort(__float2bfloat16(v[e] - __bfloat162float(hb)));
    }
    h4 = make_uint4(h[0] | (h[1] << 16), h[2] | (h[3] << 16),
                    h[4] | (h[5] << 16), h[6] | (h[7] << 16));
    l4 = make_uint4(l[0] | (l[1] << 16), l[2] | (l[3] << 16),
                    l[4] | (l[5] << 16), l[6] | (l[7] << 16));
}

// ---------------- pre-split: fp32 -> (hi, lo) bf16 ----------------
__global__ void split_fp32(const float* __restrict__ src, u16* __restrict__ hi,
                           u16* __restrict__ lo, int n4) {
    const int i = blockIdx.x * 256 + threadIdx.x;
    if (i < n4) {
        float4 v = ((const float4*)src)[i];
        uint2 h, l; cvt_split(v, h, l);
        ((uint2*)hi)[i] = h;
        ((uint2*)lo)[i] = l;
    }
}

// ---- bf16 chunk loaders: [rows x 32] (row stride ld elems) ----
template <int NU>
__device__ __forceinline__ void ldg_b(uint4 (&r)[NU], const u16* __restrict__ g,
                                      int ld, int tid) {
    #pragma unroll
    for (int i = 0; i < NU; i++) {
        const int u = tid + i * 256;
        const int row = u >> 2, c8 = (u & 3) << 3;
        r[i] = *(const uint4*)(g + (size_t)row * ld + c8);
    }
}
template <int NU>
__device__ __forceinline__ void sts_b(const uint4 (&r)[NU], u16* s, int tid) {
    #pragma unroll
    for (int i = 0; i < NU; i++) {
        const int u = tid + i * 256;
        const int row = u >> 2, c8 = (u & 3) << 3;
        *(uint4*)(s + row * SPAD + c8) = r[i];
    }
}

// fp32 chunk helpers (av P path): [128 x 32] fp32 (row stride ld)
__device__ __forceinline__ void ldg_p(float4 (&r)[4], const float* __restrict__ g,
                                      int ld, int tid) {
    #pragma unroll
    for (int i = 0; i < 4; i++) {
        const int u = tid + i * 256;
        const int row = u >> 3, c4 = (u & 7) << 2;
        r[i] = *(const float4*)(g + (size_t)row * ld + c4);
    }
}
__device__ __forceinline__ void sts_p(const float4 (&v)[4], u16* shi, u16* slo, int tid) {
    #pragma unroll
    for (int i = 0; i < 4; i++) {
        const int u = tid + i * 256;
        const int row = u >> 3, c4 = (u & 7) << 2;
        uint2 hv, lv; cvt_split(v[i], hv, lv);
        *(uint2*)(shi + row * SPAD + c4) = hv;
        *(uint2*)(slo + row * SPAD + c4) = lv;
    }
}

// [128 x 64] bf16 (ld=DKK) -> smem stride SPAD2 (scores Q/K)
__device__ __forceinline__ void ldsts_q(const u16* __restrict__ g, u16* s, int tid) {
    #pragma unroll
    for (int i = 0; i < 4; i++) {
        const int u = tid + i * 256;
        const int r = u >> 3, c8 = (u & 7) << 3;
        *(uint4*)(s + r * SPAD2 + c8) = *(const uint4*)(g + (size_t)r * DKK + c8);
    }
}
__device__ __forceinline__ void ldg_k4(uint4 (&r)[4], const u16* __restrict__ g, int tid) {
    #pragma unroll
    for (int i = 0; i < 4; i++) {
        const int u = tid + i * 256;
        r[i] = *(const uint4*)(g + (size_t)(u >> 3) * DKK + ((u & 7) << 3));
    }
}
__device__ __forceinline__ void sts_k4(const uint4 (&r)[4], u16* s, int tid) {
    #pragma unroll
    for (int i = 0; i < 4; i++) {
        const int u = tid + i * 256;
        *(uint4*)(s + (u >> 3) * SPAD2 + ((u & 7) << 3)) = r[i];
    }
}

// One K-chunk of split-bf16 3-pass MMA (AhBh + AhBl + AlBh).
template <int MT, int NT, int STRIDE, int KC>
__device__ __forceinline__ void block_mma(
    const u16* sAh, const u16* sAl, const u16* sBh, const u16* sBl,
    int a_row0, int b_row0, int lane, float (&acc)[MT][NT][4]) {
    #pragma unroll
    for (int kb = 0; kb < KC; kb += 16) {
        uint32_t ah[MT][4], al[MT][4], bh[NT][2], bl[NT][2];
        const int ar = a_row0 + (lane & 15);
        const int ac = kb + ((lane >> 4) << 3);
        #pragma unroll
        for (int i = 0; i < MT; i++) {
            LDSM_X4(ah[i], s32(sAh + (ar + i * 16) * STRIDE + ac));
            LDSM_X4(al[i], s32(sAl + (ar + i * 16) * STRIDE + ac));
        }
        const int br = b_row0 + (lane & 7);
        const int bc = kb + (((lane >> 3) & 1) << 3);
        #pragma unroll
        for (int j = 0; j < NT; j++) {
            LDSM_X2(bh[j], s32(sBh + (br + j * 8) * STRIDE + bc));
            LDSM_X2(bl[j], s32(sBl + (br + j * 8) * STRIDE + bc));
        }
        #pragma unroll
        for (int i = 0; i < MT; i++)
            #pragma unroll
            for (int j = 0; j < NT; j++) {
                mma_bf16(acc[i][j], ah[i], bh[j]);
                mma_bf16(acc[i][j], ah[i], bl[j]);
                mma_bf16(acc[i][j], al[i], bh[j]);
            }
    }
}

// Stage a 32-col accumulator group into fp32 smem [128][33].
template <int MT, int NT>
__device__ __forceinline__ void stage_group(float* stg, int warp_m, int col_base, int lane,
                                            float (&acc)[MT][NT][4]) {
    const int r0 = warp_m * MT * 16 + (lane >> 2);
    const int c0 = (lane & 3) * 2;
    #pragma unroll
    for (int i = 0; i < MT; i++)
        #pragma unroll
        for (int j = 0; j < NT; j++) {
            float* p = stg + (size_t)(r0 + i * 16) * 33 + col_base + j * 8 + c0;
            p[0] = acc[i][j][0];
            p[1] = acc[i][j][1];
            p[8 * 33 + 0] = acc[i][j][2];
            p[8 * 33 + 1] = acc[i][j][3];
        }
}

// ================= projection GEMM (bf16 hi/lo in): C = A @ W^T + bias =============
// MODE 0: headed bf16 hi/lo out [(b*16+h)][l][dk]
// MODE 1: V^T bf16 hi/lo out [(b*16+h)][dk][l]
// MODE 2: flat fp32 out[m*1024 + n]
template <int MODE>
__global__ void __launch_bounds__(256, 2)
gemm_proj(const u16* __restrict__ Ah, const u16* __restrict__ Al,
          const u16* __restrict__ Bh, const u16* __restrict__ Bl,
          const float* __restrict__ bias, float* __restrict__ fout,
          u16* __restrict__ outh, u16* __restrict__ outl) {
    extern __shared__ char sm[];
    const int tid = threadIdx.x, lane = tid & 31, wid = tid >> 5;
    const int warp_m = wid & 1, warp_n = wid >> 1;     // 2 x 4; warp tile 64x16
    const int m0 = blockIdx.y * 128, n0 = blockIdx.x * 64;

    const u16* Ahb = Ah + (size_t)m0 * DD;
    const u16* Alb = Al + (size_t)m0 * DD;
    const u16* Bhb = Bh + (size_t)n0 * DD;
    const u16* Blb = Bl + (size_t)n0 * DD;

    float acc[4][2][4] = {};
    uint4 rah[2], ral[2], rbh[1], rbl[1];

    ldg_b<2>(rah, Ahb, DD, tid); ldg_b<2>(ral, Alb, DD, tid);
    ldg_b<1>(rbh, Bhb, DD, tid); ldg_b<1>(rbl, Blb, DD, tid);
    {
        char* s0 = sm;
        sts_b<2>(rah, (u16*)(s0 + ST_AH), tid); sts_b<2>(ral, (u16*)(s0 + ST_AL), tid);
        sts_b<1>(rbh, (u16*)(s0 + ST_BH), tid); sts_b<1>(rbl, (u16*)(s0 + ST_BL), tid);
    }
    ldg_b<2>(rah, Ahb + 32, DD, tid); ldg_b<2>(ral, Alb + 32, DD, tid);
    ldg_b<1>(rbh, Bhb + 32, DD, tid); ldg_b<1>(rbl, Blb + 32, DD, tid);
    __syncthreads();

    const int NK = DD / 32;   // 32
    for (int k = 0; k < NK; k++) {
        char* cur = sm + (k & 1) * STAGE_BYTES;
        block_mma<4, 2, SPAD, 32>((u16*)(cur + ST_AH), (u16*)(cur + ST_AL),
                                  (u16*)(cur + ST_BH), (u16*)(cur + ST_BL),
                                  warp_m * 64, warp_n * 16, lane, acc);
        if (k + 1 < NK) {
            char* nxt = sm + ((k + 1) & 1) * STAGE_BYTES;
            sts_b<2>(rah, (u16*)(nxt + ST_AH), tid); sts_b<2>(ral, (u16*)(nxt + ST_AL), tid);
            sts_b<1>(rbh, (u16*)(nxt + ST_BH), tid); sts_b<1>(rbl, (u16*)(nxt + ST_BL), tid);
        }
        if (k + 2 < NK) {
            ldg_b<2>(rah, Ahb + (k + 2) * 32, DD, tid); ldg_b<2>(ral, Alb + (k + 2) * 32, DD, tid);
            ldg_b<1>(rbh, Bhb + (k + 2) * 32, DD, tid); ldg_b<1>(rbl, Blb + (k + 2) * 32, DD, tid);
        }
        __syncthreads();
    }

    float* stg = (float*)sm;
    const int b = m0 >> 11, l0 = m0 & (LL - 1);
    for (int g = 0; g < 2; g++) {
        if ((warp_n >> 1) == g)
            stage_group<4, 2>(stg, warp_m, (warp_n & 1) * 16, lane, acc);
        __syncthreads();
        const int n_base = n0 + g * 32;
        if (MODE == 2) {
            for (int u = tid; u < 1024; u += 256) {
                const int r = u >> 3, c4 = (u & 7) << 2;
                float4 v;
                v.x = stg[(size_t)r * 33 + c4 + 0] + bias[n_base + c4 + 0];
                v.y = stg[(size_t)r * 33 + c4 + 1] + bias[n_base + c4 + 1];
                v.z = stg[(size_t)r * 33 + c4 + 2] + bias[n_base + c4 + 2];
                v.w = stg[(size_t)r * 33 + c4 + 3] + bias[n_base + c4 + 3];
                *(float4*)(fout + (size_t)(m0 + r) * DD + n_base + c4) = v;
            }
        } else if (MODE == 0) {
            const int h = n_base >> 6, cc = n_base & 63;
            u16* dh = outh + ((size_t)(b * HH + h) * LL + l0) * DKK + cc;
            u16* dl = outl + ((size_t)(b * HH + h) * LL + l0) * DKK + cc;
            for (int u = tid; u < 512; u += 256) {
                const int r = u >> 2, c8 = (u & 3) << 3;
                float4 b0 = *(const float4*)(bias + n_base + c8);
                float4 b1 = *(const float4*)(bias + n_base + c8 + 4);
                float vals[8];
                #pragma unroll
                for (int e = 0; e < 4; e++) {
                    vals[e]     = stg[(size_t)r * 33 + c8 + e]     + ((const float*)&b0)[e];
                    vals[e + 4] = stg[(size_t)r * 33 + c8 + 4 + e] + ((const float*)&b1)[e];
                }
                uint4 h4, l4; split8(vals, h4, l4);
                *(uint4*)(dh + (size_t)r * DKK + c8) = h4;
                *(uint4*)(dl + (size_t)r * DKK + c8) = l4;
            }
        } else {   // MODE 1: V^T
            const int h = n_base >> 6, cc = n_base & 63;
            u16* dh = outh + ((size_t)(b * HH + h) * DKK + cc) * LL + l0;
            u16* dl = outl + ((size_t)(b * HH + h) * DKK + cc) * LL + l0;
            for (int u = tid; u < 512; u += 256) {
                const int c = u >> 4, l8 = (u & 15) << 3;
                const float bv = bias[n_base + c];
                float vals[8];
                #pragma unroll
                for (int e = 0; e < 8; e++)
                    vals[e] = stg[(size_t)(l8 + e) * 33 + c] + bv;
                uint4 h4, l4; split8(vals, h4, l4);
                *(uint4*)(dh + (size_t)c * LL + l8) = h4;
                *(uint4*)(dl + (size_t)c * LL + l8) = l4;
            }
        }
        __syncthreads();
    }
}

// ===== scores: strips of 4 kt-tiles; bf16 q/k in; direct STG.64 epilogue =====
__global__ void __launch_bounds__(256, 2)
scores_mma(const u16* __restrict__ qh, const u16* __restrict__ ql,
           const u16* __restrict__ kh, const u16* __restrict__ kl,
           float* __restrict__ attn) {
    const int strip = blockIdx.x, qt = blockIdx.y, bhid = blockIdx.z;
    const int kt0 = strip * 4;
    const int q0 = qt * 128;
    extern __shared__ char sm[];
    const int tid = threadIdx.x, lane = tid & 31, wid = tid >> 5;
    const int warp_m = wid & 1, warp_n = wid >> 1;     // 2 x 4; warp tile 64x32

    float* attnb = attn + ((size_t)bhid * LL + q0) * LL;

    if (kt0 > qt) {
        const float4 z = make_float4(0.f, 0.f, 0.f, 0.f);
        for (int u = tid; u < 128 * 128; u += 256) {
            const int r = u >> 7, c4 = (u & 127) << 2;
            *(float4*)(attnb + (size_t)r * LL + kt0 * 128 + c4) = z;
        }
        return;
    }

    const size_t qoff = ((size_t)bhid * LL + q0) * DKK;
    ldsts_q(qh + qoff, (u16*)(sm + SC_QH), tid);
    ldsts_q(ql + qoff, (u16*)(sm + SC_QL), tid);
    uint4 kbh[4], kbl[4];
    {
        const size_t koff = ((size_t)bhid * LL + kt0 * 128) * DKK;
        ldg_k4(kbh, kh + koff, tid);
        ldg_k4(kbl, kl + koff, tid);
    }
    __syncthreads();

    const int rbase = warp_m * 64 + (lane >> 2);
    const int cbase = warp_n * 32 + (lane & 3) * 2;

    for (int kt = kt0; kt < kt0 + 4; kt++) {
        if (kt <= qt) {
            sts_k4(kbh, (u16*)(sm + SC_KH), tid);
            sts_k4(kbl, (u16*)(sm + SC_KL), tid);
            __syncthreads();

            float acc[4][4][4] = {};
            block_mma<4, 4, SPAD2, 64>((u16*)(sm + SC_QH), (u16*)(sm + SC_QL),
                                       (u16*)(sm + SC_KH), (u16*)(sm + SC_KL),
                                       warp_m * 64, warp_n * 32, lane, acc);

            if (kt + 1 <= qt && kt + 1 < kt0 + 4) {
                const size_t koff = ((size_t)bhid * LL + (kt + 1) * 128) * DKK;
                ldg_k4(kbh, kh + koff, tid);
                ldg_k4(kbl, kl + koff, tid);
            }

            // direct STG.64 epilogue
            #pragma unroll
            for (int i = 0; i < 4; i++)
                #pragma unroll
                for (int p = 0; p < 2; p++) {
                    const int r = rbase + i * 16 + p * 8;
                    float* rowp = attnb + (size_t)r * LL + kt * 128 + cbase;
                    #pragma unroll
                    for (int j = 0; j < 4; j++) {
                        float2 v = make_float2(acc[i][j][p * 2] * 0.125f,
                                               acc[i][j][p * 2 + 1] * 0.125f);
                        *(float2*)(rowp + j * 8) = v;
                    }
                }
            __syncthreads();   // K buffer reuse guard
        } else {
            const float4 z = make_float4(0.f, 0.f, 0.f, 0.f);
            for (int u = tid; u < 128 * 32; u += 256) {
                const int r = u >> 5, c4 = (u & 31) << 2;
                *(float4*)(attnb + (size_t)r * LL + kt * 128 + c4) = z;
            }
        }
    }
}

// ================= row softmax (causal, bounded to qt-tile-aligned end) ============
__global__ void softmax_kernel(float* __restrict__ attn) {
    const int row = blockIdx.x, bh = blockIdx.y;
    float* p = attn + ((size_t)bh * LL + row) * LL;
    const int valid = row + 1;
    const int nend = (((row >> 7) + 1) << 7);
    const int tid = threadIdx.x;

    __shared__ float sred[8];

    float4 v[2];
    float m = -3.4e38f;
    #pragma unroll
    for (int i = 0; i < 2; i++) {
        const int j = (tid + i * 256) * 4;
        if (j < nend) {
            v[i] = *(const float4*)(p + j);
            if (j + 0 < valid) m = fmaxf(m, v[i].x);
            if (j + 1 < valid) m = fmaxf(m, v[i].y);
            if (j + 2 < valid) m = fmaxf(m, v[i].z);
            if (j + 3 < valid) m = fmaxf(m, v[i].w);
        }
    }
    #pragma unroll
    for (int o = 16; o > 0; o >>= 1) m = fmaxf(m, __shfl_xor_sync(0xffffffff, m, o));
    if ((tid & 31) == 0) sred[tid >> 5] = m;
    __syncthreads();
    m = sred[0];
    #pragma unroll
    for (int w = 1; w < 8; w++) m = fmaxf(m, sred[w]);

    float sum = 0.0f;
    #pragma unroll
    for (int i = 0; i < 2; i++) {
        const int j = (tid + i * 256) * 4;
        if (j < nend) {
            v[i].x = (j + 0 < valid) ? __expf(v[i].x - m) : 0.0f;
            v[i].y = (j + 1 < valid) ? __expf(v[i].y - m) : 0.0f;
            v[i].z = (j + 2 < valid) ? __expf(v[i].z - m) : 0.0f;
            v[i].w = (j + 3 < valid) ? __expf(v[i].w - m) : 0.0f;
            sum += v[i].x + v[i].y + v[i].z + v[i].w;
        }
    }
    __syncthreads();
    #pragma unroll
    for (int o = 16; o > 0; o >>= 1) sum += __shfl_xor_sync(0xffffffff, sum, o);
    if ((tid & 31) == 0) sred[tid >> 5] = sum;
    __syncthreads();
    sum = 0.0f;
    #pragma unroll
    for (int w = 0; w < 8; w++) sum += sred[w];
    const float inv = 1.0f / sum;

    #pragma unroll
    for (int i = 0; i < 2; i++) {
        const int j = (tid + i * 256) * 4;
        if (j < nend) {
            float4 o4;
            o4.x = v[i].x * inv; o4.y = v[i].y * inv;
            o4.z = v[i].z * inv; o4.w = v[i].w * inv;
            *(float4*)(p + j) = o4;
        }
    }
}

// ========= O = P @ V (bf16 V in; oc out pre-split; heavy-first; pipelined) =========
__global__ void __launch_bounds__(256, 2)
av_mma(const float* __restrict__ attn, const u16* __restrict__ vth,
       const u16* __restrict__ vtl, u16* __restrict__ och, u16* __restrict__ ocl) {
    const int qt = (gridDim.x - 1) - blockIdx.x;
    const int bhid = blockIdx.y;
    const int b = bhid >> 4, h = bhid & 15;
    extern __shared__ char sm[];
    const int tid = threadIdx.x, lane = tid & 31, wid = tid >> 5;
    const int warp_m = wid & 1, warp_n = wid >> 1;
    const int q0 = qt * 128;

    const float* Pb = attn + ((size_t)bhid * LL + q0) * LL;
    const u16* Vhb = vth + (size_t)bhid * DKK * LL;
    const u16* Vlb = vtl + (size_t)bhid * DKK * LL;

    float acc[4][2][4] = {};
    float4 ra[4];
    uint4 rvh[1], rvl[1];

    const int NK = (qt + 1) * 4;

    ldg_p(ra, Pb, LL, tid);
    ldg_b<1>(rvh, Vhb, LL, tid); ldg_b<1>(rvl, Vlb, LL, tid);
    {
        char* s0 = sm;
        sts_p(ra, (u16*)(s0 + ST_AH), (u16*)(s0 + ST_AL), tid);
        sts_b<1>(rvh, (u16*)(s0 + ST_BH), tid); sts_b<1>(rvl, (u16*)(s0 + ST_BL), tid);
    }
    ldg_p(ra, Pb + 32, LL, tid);
    ldg_b<1>(rvh, Vhb + 32, LL, tid); ldg_b<1>(rvl, Vlb + 32, LL, tid);
    __syncthreads();

    for (int k = 0; k < NK; k++) {
        char* cur = sm + (k & 1) * STAGE_BYTES;
        block_mma<4, 2, SPAD, 32>((u16*)(cur + ST_AH), (u16*)(cur + ST_AL),
                                  (u16*)(cur + ST_BH), (u16*)(cur + ST_BL),
                                  warp_m * 64, warp_n * 16, lane, acc);
        if (k + 1 < NK) {
            char* nxt = sm + ((k + 1) & 1) * STAGE_BYTES;
            sts_p(ra, (u16*)(nxt + ST_AH), (u16*)(nxt + ST_AL), tid);
            sts_b<1>(rvh, (u16*)(nxt + ST_BH), tid); sts_b<1>(rvl, (u16*)(nxt + ST_BL), tid);
        }
        if (k + 2 < NK) {
            ldg_p(ra, Pb + (k + 2) * 32, LL, tid);
            ldg_b<1>(rvh, Vhb + (k + 2) * 32, LL, tid);
            ldg_b<1>(rvl, Vlb + (k + 2) * 32, LL, tid);
        }
        __syncthreads();
    }

    // direct epilogue: split acc to oc hi/lo (concat layout)
    const int rbase = warp_m * 64 + (lane >> 2);
    const int cbase = warp_n * 16 + (lane & 3) * 2;
    #pragma unroll
    for (int i = 0; i < 4; i++)
        #pragma unroll
        for (int p = 0; p < 2; p++) {
            const int r = rbase + i * 16 + p * 8;
            const size_t base = (size_t)(b * LL + q0 + r) * DD + h * DKK + cbase;
            #pragma unroll
            for (int j = 0; j < 2; j++) {
                const float w0 = acc[i][j][p * 2], w1 = acc[i][j][p * 2 + 1];
                __nv_bfloat16 h0 = __float2bfloat16(w0), h1 = __float2bfloat16(w1);
                __nv_bfloat16 l0 = __float2bfloat16(w0 - __bfloat162float(h0));
                __nv_bfloat16 l1 = __float2bfloat16(w1 - __bfloat162float(h1));
                *(uint32_t*)(och + base + j * 8) =
                    ((uint32_t)__bfloat16_as_ushort(h1) << 16) | __bfloat16_as_ushort(h0);
                *(uint32_t*)(ocl + base + j * 8) =
                    ((uint32_t)__bfloat16_as_ushort(l1) << 16) | __bfloat16_as_ushort(l0);
            }
        }
}

// ---------------- launch ----------------
extern "C" void kernel_launch(void* const* d_in, const int* in_sizes, int n_in,
                              void* d_out, int out_size) {
    const float* x  = (const float*)d_in[0];
    const float* Wq = (const float*)d_in[2];
    const float* bq = (const float*)d_in[3];
    const float* Wk = (const float*)d_in[4];
    const float* bk = (const float*)d_in[5];
    const float* Wv = (const float*)d_in[6];
    const float* bv = (const float*)d_in[7];
    const float* Wo = (const float*)d_in[8];
    const float* bo = (const float*)d_in[9];
    float* out = (float*)d_out;

    const size_t out_elems  = (size_t)BB * LL * DD;
    const size_t attn_elems = (size_t)BH * LL * LL;

    u16 *xh, *xl, *wh, *wl, *qh, *ql, *kh, *kl, *vth, *vtl, *och, *ocl;
    float* attn;
    cudaGetSymbolAddress((void**)&xh,  g_xh);  cudaGetSymbolAddress((void**)&xl,  g_xl);
    cudaGetSymbolAddress((void**)&wh,  g_wh);  cudaGetSymbolAddress((void**)&wl,  g_wl);
    cudaGetSymbolAddress((void**)&qh,  g_qh);  cudaGetSymbolAddress((void**)&ql,  g_ql);
    cudaGetSymbolAddress((void**)&kh,  g_kh);  cudaGetSymbolAddress((void**)&kl,  g_kl);
    cudaGetSymbolAddress((void**)&vth, g_vth); cudaGetSymbolAddress((void**)&vtl, g_vtl);
    cudaGetSymbolAddress((void**)&och, g_och); cudaGetSymbolAddress((void**)&ocl, g_ocl);
    if ((size_t)out_size >= out_elems + attn_elems) {
        attn = out + out_elems;
    } else {
        cudaGetSymbolAddress((void**)&attn, g_attn_scratch);
    }

    cudaFuncSetAttribute(gemm_proj<0>, cudaFuncAttributeMaxDynamicSharedMemorySize, PIPE_SMEM);
    cudaFuncSetAttribute(gemm_proj<1>, cudaFuncAttributeMaxDynamicSharedMemorySize, PIPE_SMEM);
    cudaFuncSetAttribute(gemm_proj<2>, cudaFuncAttributeMaxDynamicSharedMemorySize, PIPE_SMEM);
    cudaFuncSetAttribute(scores_mma,   cudaFuncAttributeMaxDynamicSharedMemorySize, SC_SMEM);
    cudaFuncSetAttribute(av_mma,       cudaFuncAttributeMaxDynamicSharedMemorySize, PIPE_SMEM);

    // pre-split x and weights
    const int xw4 = (MROWS * DD) / 4;      // 2097152
    const int ww4 = (DD * DD) / 4;         // 262144
    split_fp32<<<(xw4 + 255) / 256, 256>>>(x,  xh, xl, xw4);
    split_fp32<<<(ww4 + 255) / 256, 256>>>(Wq, wh + (size_t)0 * DD * DD, wl + (size_t)0 * DD * DD, ww4);
    split_fp32<<<(ww4 + 255) / 256, 256>>>(Wk, wh + (size_t)1 * DD * DD, wl + (size_t)1 * DD * DD, ww4);
    split_fp32<<<(ww4 + 255) / 256, 256>>>(Wv, wh + (size_t)2 * DD * DD, wl + (size_t)2 * DD * DD, ww4);
    split_fp32<<<(ww4 + 255) / 256, 256>>>(Wo, wh + (size_t)3 * DD * DD, wl + (size_t)3 * DD * DD, ww4);

    dim3 projGrid(DD / 64, MROWS / 128);       // (16, 64)
    gemm_proj<0><<<projGrid, 256, PIPE_SMEM>>>(xh, xl, wh + (size_t)0 * DD * DD, wl + (size_t)0 * DD * DD,
                                               bq, nullptr, qh, ql);
    gemm_proj<0><<<projGrid, 256, PIPE_SMEM>>>(xh, xl, wh + (size_t)1 * DD * DD, wl + (size_t)1 * DD * DD,
                                               bk, nullptr, kh, kl);
    gemm_proj<1><<<projGrid, 256, PIPE_SMEM>>>(xh, xl, wh + (size_t)2 * DD * DD, wl + (size_t)2 * DD * DD,
                                               bv, nullptr, vth, vtl);

    dim3 scoreGrid(4, LL / 128, BH);           // (4, 16, 64)
    scores_mma<<<scoreGrid, 256, SC_SMEM>>>(qh, ql, kh, kl, attn);

    dim3 smGrid(LL, BH);
    softmax_kernel<<<smGrid, 256>>>(attn);

    dim3 avGrid(LL / 128, BH);                 // (16, 64)
    av_mma<<<avGrid, 256, PIPE_SMEM>>>(attn, vth, vtl, och, ocl);

    gemm_proj<2><<<projGrid, 256, PIPE_SMEM>>>(och, ocl, wh + (size_t)3 * DD * DD, wl + (size_t)3 * DD * DD,
                                               bo, out, nullptr, nullptr);
}